// round 1
// baseline (speedup 1.0000x reference)
#include <cuda_runtime.h>
#include <cstdint>
#include <math.h>

#define T 8192
#define H 2048
#define IDIM 2816
#define NE 16
#define R1 128

#define BM 128
#define BN 64
#define BK 32
#define BKP 36   // padded K stride (floats): conflict-free fragment loads

// ---------------- device scratch (static, no allocations) ----------------
__device__ float g_tanh[(size_t)T * R1];                 // 4 MB   tanh(x @ wg1^T)
__device__ int   g_list[NE * T];                         // token id per (expert, slot)
__device__ float g_wgt[NE * T];                          // routing weight per slot
__device__ int   g_cnt[NE];
__device__ int   g_base[NE];
__device__ float g_h[(size_t)(2 * T + 128) * IDIM];      // 186 MB  SwiGLU activations

// ---------------- small helpers ----------------
__device__ __forceinline__ uint32_t f2tf32(float f) {
    uint32_t u;
    asm("cvt.rna.tf32.f32 %0, %1;" : "=r"(u) : "f"(f));
    return u;
}

__device__ __forceinline__ void mma8(float* d, const uint32_t* a, const uint32_t* b) {
    asm volatile(
        "mma.sync.aligned.m16n8k8.row.col.f32.tf32.tf32.f32 "
        "{%0,%1,%2,%3},{%4,%5,%6,%7},{%8,%9},{%0,%1,%2,%3};\n"
        : "+f"(d[0]), "+f"(d[1]), "+f"(d[2]), "+f"(d[3])
        : "r"(a[0]), "r"(a[1]), "r"(a[2]), "r"(a[3]), "r"(b[0]), "r"(b[1]));
}

__device__ __forceinline__ void cp16(uint32_t dst, const float* src) {
    asm volatile("cp.async.cg.shared.global [%0], [%1], 16;\n" :: "r"(dst), "l"(src));
}
__device__ __forceinline__ void cpcommit() { asm volatile("cp.async.commit_group;\n" ::); }
__device__ __forceinline__ void cpwait1()  { asm volatile("cp.async.wait_group 1;\n" ::); }

// ---------------- K0: zero expert counters ----------------
__global__ void k_zero() {
    if (threadIdx.x < NE) g_cnt[threadIdx.x] = 0;
}

// ---------------- K1: router layer 1 (fp32 SIMT GEMM + tanh) ----------------
// g_tanh[t, n] = tanh( x[t, :] . wg1[n, :] ),  n in [0,128)
__global__ void __launch_bounds__(256) k_router(const float* __restrict__ x,
                                                const float* __restrict__ wg1) {
    __shared__ float As[16][68];    // [k][m], padded
    __shared__ float Bs[16][132];   // [k][n], padded
    const int m0  = blockIdx.x * 64;
    const int tid = threadIdx.x;
    const int r0  = (tid >> 4) * 4;   // 16 row groups * 4 rows
    const int c0  = (tid & 15) * 8;   // 16 col groups * 8 cols

    float acc[4][8];
#pragma unroll
    for (int r = 0; r < 4; r++)
#pragma unroll
        for (int c = 0; c < 8; c++) acc[r][c] = 0.f;

    for (int k0 = 0; k0 < H; k0 += 16) {
        {   // stage A: 64 rows x 16 k  (transposed into smem)
            int row = tid >> 2, q = tid & 3;
            float4 v = *(const float4*)(x + (size_t)(m0 + row) * H + k0 + q * 4);
            As[q * 4 + 0][row] = v.x; As[q * 4 + 1][row] = v.y;
            As[q * 4 + 2][row] = v.z; As[q * 4 + 3][row] = v.w;
        }
#pragma unroll
        for (int i = 0; i < 2; i++) {  // stage B: 128 rows(n) x 16 k
            int lin = tid + i * 256, n = lin >> 2, q = lin & 3;
            float4 v = *(const float4*)(wg1 + (size_t)n * H + k0 + q * 4);
            Bs[q * 4 + 0][n] = v.x; Bs[q * 4 + 1][n] = v.y;
            Bs[q * 4 + 2][n] = v.z; Bs[q * 4 + 3][n] = v.w;
        }
        __syncthreads();
#pragma unroll
        for (int kk = 0; kk < 16; kk++) {
            float a[4], b[8];
            *(float4*)a       = *(const float4*)&As[kk][r0];
            *(float4*)b       = *(const float4*)&Bs[kk][c0];
            *(float4*)(b + 4) = *(const float4*)&Bs[kk][c0 + 4];
#pragma unroll
            for (int r = 0; r < 4; r++)
#pragma unroll
                for (int c = 0; c < 8; c++) acc[r][c] += a[r] * b[c];
        }
        __syncthreads();
    }
#pragma unroll
    for (int r = 0; r < 4; r++)
#pragma unroll
        for (int c = 0; c < 8; c++)
            g_tanh[(size_t)(m0 + r0 + r) * R1 + c0 + c] = tanhf(acc[r][c]);
}

// ---------------- K2: router layer 2 + top-2 + routing tables ----------------
__global__ void k_topk(const float* __restrict__ wg2) {
    const int tok  = blockIdx.x * 8 + (threadIdx.x >> 5);
    const int lane = threadIdx.x & 31;
    float acc[NE];
#pragma unroll
    for (int e = 0; e < NE; e++) acc[e] = 0.f;
    const float* tv = g_tanh + (size_t)tok * R1;
#pragma unroll
    for (int j = 0; j < 4; j++) {
        float v = tv[lane + 32 * j];
#pragma unroll
        for (int e = 0; e < NE; e++) acc[e] += v * __ldg(&wg2[e * R1 + lane + 32 * j]);
    }
#pragma unroll
    for (int e = 0; e < NE; e++) {
        acc[e] += __shfl_xor_sync(0xffffffffu, acc[e], 16);
        acc[e] += __shfl_xor_sync(0xffffffffu, acc[e], 8);
        acc[e] += __shfl_xor_sync(0xffffffffu, acc[e], 4);
        acc[e] += __shfl_xor_sync(0xffffffffu, acc[e], 2);
        acc[e] += __shfl_xor_sync(0xffffffffu, acc[e], 1);
    }
    if (lane == 0) {
        // top-1 / top-2 with first-occurrence tie break (matches lax.top_k)
        int i1 = 0; float v1 = acc[0];
#pragma unroll
        for (int e = 1; e < NE; e++) if (acc[e] > v1) { v1 = acc[e]; i1 = e; }
        int i2 = -1; float v2 = -3.4e38f;
#pragma unroll
        for (int e = 0; e < NE; e++) if (e != i1 && acc[e] > v2) { v2 = acc[e]; i2 = e; }
        // renormalized softmax weights over the pair (full softmax denom cancels)
        float w1 = 1.f / (1.f + expf(v2 - v1));
        float w2 = 1.f / (1.f + expf(v1 - v2));
        int s1 = atomicAdd(&g_cnt[i1], 1);
        g_list[i1 * T + s1] = tok; g_wgt[i1 * T + s1] = w1;
        int s2 = atomicAdd(&g_cnt[i2], 1);
        g_list[i2 * T + s2] = tok; g_wgt[i2 * T + s2] = w2;
    }
}

// ---------------- K3: exclusive prefix of counts ----------------
__global__ void k_base() {
    int s = 0;
    for (int e = 0; e < NE; e++) { g_base[e] = s; s += g_cnt[e]; }
}

// ---------------- K4: gate+up GEMM (tf32) fused with SwiGLU ----------------
// h[row, n] = silu(X@Wg^T) * (X@Wu^T), X = gathered tokens of expert e
__global__ void __launch_bounds__(256, 2) k_gemm1(const float* __restrict__ x,
                                                  const float* __restrict__ w_up) {
    const int e   = blockIdx.z;
    const int cnt = g_cnt[e];
    const int m0  = blockIdx.y * BM;
    if (m0 >= cnt) return;
    const int n0   = blockIdx.x * BN;
    const int base = g_base[e];

    extern __shared__ float sm[];
    float* As = sm;                    // [2][BM][BKP]
    float* Bs = sm + 2 * BM * BKP;     // [2][2][BN][BKP]  (gate, up)

    const int tid  = threadIdx.x;
    const int lane = tid & 31;
    const int warp = tid >> 5;
    const int wm = warp & 3, wn = warp >> 2;    // 4x2 warp grid, 32x32 warp tiles
    const int g = lane >> 2, t = lane & 3;
    const int kq = tid & 7, arow = tid >> 3;

    const float* aSrc[4]; uint32_t aDst[4];
#pragma unroll
    for (int i = 0; i < 4; i++) {
        int r = arow + 32 * i;
        int grow = m0 + r; if (grow > cnt - 1) grow = cnt - 1;   // clamp (output guarded)
        int tok = g_list[e * T + grow];
        aSrc[i] = x + (size_t)tok * H + kq * 4;
        aDst[i] = (uint32_t)__cvta_generic_to_shared(As + r * BKP + kq * 4);
    }
    const float* bSrc[2][2]; uint32_t bDst[2][2];
    const float* wb = w_up + (size_t)e * 2 * IDIM * H;
#pragma unroll
    for (int i = 0; i < 2; i++) {
        int r = arow + 32 * i;   // 0..63
        bSrc[0][i] = wb + (size_t)(n0 + r) * H + kq * 4;
        bSrc[1][i] = wb + (size_t)(IDIM + n0 + r) * H + kq * 4;
        bDst[0][i] = (uint32_t)__cvta_generic_to_shared(Bs + r * BKP + kq * 4);
        bDst[1][i] = (uint32_t)__cvta_generic_to_shared(Bs + (BN + r) * BKP + kq * 4);
    }
    const uint32_t aStB = BM * BKP * 4;
    const uint32_t bStB = 2 * BN * BKP * 4;

    float dg[2][4][4], du[2][4][4];
#pragma unroll
    for (int a = 0; a < 2; a++)
#pragma unroll
        for (int b = 0; b < 4; b++)
#pragma unroll
            for (int c = 0; c < 4; c++) { dg[a][b][c] = 0.f; du[a][b][c] = 0.f; }

    // prologue: stage 0
#pragma unroll
    for (int i = 0; i < 4; i++) cp16(aDst[i], aSrc[i]);
#pragma unroll
    for (int m = 0; m < 2; m++)
#pragma unroll
        for (int i = 0; i < 2; i++) cp16(bDst[m][i], bSrc[m][i]);
    cpcommit();

    const int NK = H / BK;  // 64
    for (int it = 0; it < NK; ++it) {
        const int buf = it & 1;
        if (it + 1 < NK) {
            const int nb = buf ^ 1, k0 = (it + 1) * BK;
#pragma unroll
            for (int i = 0; i < 4; i++) cp16(aDst[i] + nb * aStB, aSrc[i] + k0);
#pragma unroll
            for (int m = 0; m < 2; m++)
#pragma unroll
                for (int i = 0; i < 2; i++) cp16(bDst[m][i] + nb * bStB, bSrc[m][i] + k0);
        }
        cpcommit();
        cpwait1();
        __syncthreads();
        const float* A  = As + buf * BM * BKP;
        const float* Bg = Bs + buf * 2 * BN * BKP;
        const float* Bu = Bg + BN * BKP;
#pragma unroll
        for (int ks = 0; ks < BK; ks += 8) {
            uint32_t af[2][4];
#pragma unroll
            for (int mi = 0; mi < 2; mi++) {
                int row = wm * 32 + mi * 16 + g;
                af[mi][0] = f2tf32(A[row * BKP + ks + t]);
                af[mi][1] = f2tf32(A[(row + 8) * BKP + ks + t]);
                af[mi][2] = f2tf32(A[row * BKP + ks + t + 4]);
                af[mi][3] = f2tf32(A[(row + 8) * BKP + ks + t + 4]);
            }
#pragma unroll
            for (int ni = 0; ni < 4; ni++) {
                int col = wn * 32 + ni * 8 + g;
                uint32_t bf[2];
                bf[0] = f2tf32(Bg[col * BKP + ks + t]);
                bf[1] = f2tf32(Bg[col * BKP + ks + t + 4]);
                mma8(dg[0][ni], af[0], bf);
                mma8(dg[1][ni], af[1], bf);
                bf[0] = f2tf32(Bu[col * BKP + ks + t]);
                bf[1] = f2tf32(Bu[col * BKP + ks + t + 4]);
                mma8(du[0][ni], af[0], bf);
                mma8(du[1][ni], af[1], bf);
            }
        }
        __syncthreads();
    }

    // epilogue: SwiGLU -> g_h
#pragma unroll
    for (int mi = 0; mi < 2; mi++) {
#pragma unroll
        for (int p = 0; p < 2; p++) {
            int rl = wm * 32 + mi * 16 + g + p * 8;
            if (m0 + rl < cnt) {
                size_t rb = (size_t)(base + m0 + rl) * IDIM + n0;
#pragma unroll
                for (int ni = 0; ni < 4; ni++) {
                    int col = wn * 32 + ni * 8 + t * 2;
                    float g0 = dg[mi][ni][p * 2], g1 = dg[mi][ni][p * 2 + 1];
                    float u0 = du[mi][ni][p * 2], u1 = du[mi][ni][p * 2 + 1];
                    float h0 = g0 / (1.f + expf(-g0)) * u0;
                    float h1 = g1 / (1.f + expf(-g1)) * u1;
                    *(float2*)(g_h + rb + col) = make_float2(h0, h1);
                }
            }
        }
    }
}

// ---------------- K5: down GEMM (tf32) + weighted atomic combine ----------------
__global__ void __launch_bounds__(256, 2) k_gemm2(const float* __restrict__ w_down,
                                                  float* __restrict__ out) {
    const int e   = blockIdx.z;
    const int cnt = g_cnt[e];
    const int m0  = blockIdx.y * BM;
    if (m0 >= cnt) return;
    const int n0   = blockIdx.x * BN;
    const int base = g_base[e];

    extern __shared__ float sm[];
    float* As = sm;                    // [2][BM][BKP]
    float* Bs = sm + 2 * BM * BKP;     // [2][BN][BKP]

    const int tid  = threadIdx.x;
    const int lane = tid & 31;
    const int warp = tid >> 5;
    const int wm = warp & 3, wn = warp >> 2;
    const int g = lane >> 2, t = lane & 3;
    const int kq = tid & 7, arow = tid >> 3;

    const float* aSrc[4]; uint32_t aDst[4];
#pragma unroll
    for (int i = 0; i < 4; i++) {
        int r = arow + 32 * i;
        int grow = m0 + r; if (grow > cnt - 1) grow = cnt - 1;
        aSrc[i] = g_h + (size_t)(base + grow) * IDIM + kq * 4;
        aDst[i] = (uint32_t)__cvta_generic_to_shared(As + r * BKP + kq * 4);
    }
    const float* bSrc[2]; uint32_t bDst[2];
    const float* wb = w_down + (size_t)e * H * IDIM;
#pragma unroll
    for (int i = 0; i < 2; i++) {
        int r = arow + 32 * i;
        bSrc[i] = wb + (size_t)(n0 + r) * IDIM + kq * 4;
        bDst[i] = (uint32_t)__cvta_generic_to_shared(Bs + r * BKP + kq * 4);
    }
    const uint32_t aStB = BM * BKP * 4;
    const uint32_t bStB = BN * BKP * 4;

    float d[2][4][4];
#pragma unroll
    for (int a = 0; a < 2; a++)
#pragma unroll
        for (int b = 0; b < 4; b++)
#pragma unroll
            for (int c = 0; c < 4; c++) d[a][b][c] = 0.f;

#pragma unroll
    for (int i = 0; i < 4; i++) cp16(aDst[i], aSrc[i]);
#pragma unroll
    for (int i = 0; i < 2; i++) cp16(bDst[i], bSrc[i]);
    cpcommit();

    const int NK = IDIM / BK;  // 88
    for (int it = 0; it < NK; ++it) {
        const int buf = it & 1;
        if (it + 1 < NK) {
            const int nb = buf ^ 1, k0 = (it + 1) * BK;
#pragma unroll
            for (int i = 0; i < 4; i++) cp16(aDst[i] + nb * aStB, aSrc[i] + k0);
#pragma unroll
            for (int i = 0; i < 2; i++) cp16(bDst[i] + nb * bStB, bSrc[i] + k0);
        }
        cpcommit();
        cpwait1();
        __syncthreads();
        const float* A = As + buf * BM * BKP;
        const float* B = Bs + buf * BN * BKP;
#pragma unroll
        for (int ks = 0; ks < BK; ks += 8) {
            uint32_t af[2][4];
#pragma unroll
            for (int mi = 0; mi < 2; mi++) {
                int row = wm * 32 + mi * 16 + g;
                af[mi][0] = f2tf32(A[row * BKP + ks + t]);
                af[mi][1] = f2tf32(A[(row + 8) * BKP + ks + t]);
                af[mi][2] = f2tf32(A[row * BKP + ks + t + 4]);
                af[mi][3] = f2tf32(A[(row + 8) * BKP + ks + t + 4]);
            }
#pragma unroll
            for (int ni = 0; ni < 4; ni++) {
                int col = wn * 32 + ni * 8 + g;
                uint32_t bf[2];
                bf[0] = f2tf32(B[col * BKP + ks + t]);
                bf[1] = f2tf32(B[col * BKP + ks + t + 4]);
                mma8(d[0][ni], af[0], bf);
                mma8(d[1][ni], af[1], bf);
            }
        }
        __syncthreads();
    }

#pragma unroll
    for (int mi = 0; mi < 2; mi++) {
#pragma unroll
        for (int p = 0; p < 2; p++) {
            int rl = wm * 32 + mi * 16 + g + p * 8;
            if (m0 + rl < cnt) {
                int tok = g_list[e * T + m0 + rl];
                float w = g_wgt[e * T + m0 + rl];
                float* op = out + (size_t)tok * H + n0;
#pragma unroll
                for (int ni = 0; ni < 4; ni++) {
                    int col = wn * 32 + ni * 8 + t * 2;
                    atomicAdd(op + col,     w * d[mi][ni][p * 2]);
                    atomicAdd(op + col + 1, w * d[mi][ni][p * 2 + 1]);
                }
            }
        }
    }
}

// ---------------- launch ----------------
extern "C" void kernel_launch(void* const* d_in, const int* in_sizes, int n_in,
                              void* d_out, int out_size) {
    const float* x      = (const float*)d_in[0];
    const float* wg1    = (const float*)d_in[1];
    const float* wg2    = (const float*)d_in[2];
    const float* w_up   = (const float*)d_in[3];
    const float* w_down = (const float*)d_in[4];
    float* out = (float*)d_out;

    const int smem1 = (2 * BM * BKP + 4 * BN * BKP) * 4;  // 73728
    const int smem2 = (2 * BM * BKP + 2 * BN * BKP) * 4;  // 55296
    cudaFuncSetAttribute(k_gemm1, cudaFuncAttributeMaxDynamicSharedMemorySize, smem1);
    cudaFuncSetAttribute(k_gemm2, cudaFuncAttributeMaxDynamicSharedMemorySize, smem2);

    cudaMemsetAsync(out, 0, (size_t)T * H * sizeof(float));
    k_zero<<<1, 32>>>();
    k_router<<<T / 64, 256>>>(x, wg1);
    k_topk<<<T / 8, 256>>>(wg2);
    k_base<<<1, 1>>>();
    k_gemm1<<<dim3(IDIM / BN, T / BM, NE), 256, smem1>>>(x, w_up);
    k_gemm2<<<dim3(H / BN, T / BM, NE), 256, smem2>>>(w_down, out);
}